// round 6
// baseline (speedup 1.0000x reference)
#include <cuda_runtime.h>
#include <cuda_bf16.h>
#include <mma.h>
#include <math.h>
#include <float.h>
#include <stdint.h>

using namespace nvcuda;

// ----------------------------------------------------------------------------
// GATv2 x2 + mean-pool + classifier, dense-pair formulation.
// N=201, E=40200 (+201 self loops), D=1024 = 8 heads x 128 ch.
// GEMMs: WMMA bf16 hi/lo split x3 (tcgen05 unavailable: harness targets sm_103).
// Score+softmax+aggregation fused into one kernel per layer.
// ----------------------------------------------------------------------------

#define NN   201
#define EE   40200
#define DD   1024
#define HH   8
#define CC   128
#define NPJ  224
#define NPAD 204

// -------- scratch (device globals; no allocation allowed) -------------------
__device__ __align__(16) float g_XL[NPAD * DD];
__device__ __align__(16) float g_XR[NPAD * DD];
__device__ __align__(16) float g_H [NPAD * DD];
__device__ __align__(16) float g_H2[NPAD * DD];
__device__ int   g_cnt[NN * NPJ];
__device__ int   g_estride;
__device__ __align__(16) float g_avg[DD];

// ---------------------------------------------------------------------------
// init / edge count
// ---------------------------------------------------------------------------
__global__ void k_init(const int* __restrict__ eb) {
    int idx = blockIdx.x * blockDim.x + threadIdx.x;
    if (idx == 0) {
        int st = 2;  // assume int64 (low word = value, high word = 0)
        for (int e = 0; e < 64; e++)
            if (eb[2 * e + 1] != 0) { st = 1; break; }
        g_estride = st;
    }
    if (idx < NN * NPJ) {
        int r = idx / NPJ, c = idx - r * NPJ;
        g_cnt[idx] = (r == c && r < NN) ? 1 : 0;
    }
}

__global__ void k_count(const int* __restrict__ eb) {
    int e = blockIdx.x * blockDim.x + threadIdx.x;
    if (e < EE) {
        int st  = g_estride;
        int src = eb[e * st];
        int dst = eb[(EE + e) * st];
        atomicAdd(&g_cnt[dst * NPJ + src], 1);
    }
}

// ---------------------------------------------------------------------------
// WMMA bf16 GEMM, double-buffered: O[m][n] = sum_k X[m][k]*W[n][k] + b[n]
// CTA tile 64x64, K chunk 32, 2-deep smem pipeline, hi/lo split x3.
// grid = (4 m-tiles, 16 n-tiles, 2 sides); 256 threads (8 warps, 32x16 each).
// ---------------------------------------------------------------------------
#define A_LDM 40           // 32 k + 8 pad (bf16)
#define C_LDM 72           // 64 n + 8 pad (fp32)
#define BUF_ELEMS (4 * 64 * A_LDM)          // Ah|Al|Bh|Bl, one pipeline stage

__global__ void __launch_bounds__(256) k_gemm_mma(
    const float* __restrict__ Xin,
    const float* __restrict__ Wl, const float* __restrict__ bl,
    const float* __restrict__ Wr, const float* __restrict__ br)
{
    __shared__ __align__(16) char smem_raw[2 * BUF_ELEMS * 2];

    const float* X = Xin ? Xin : g_H;
    const int side = blockIdx.z;
    const float* W = side ? Wr : Wl;
    const float* b = side ? br : bl;
    float*       O = side ? g_XR : g_XL;
    const int m0 = blockIdx.x * 64;
    const int n0 = blockIdx.y * 64;

    const int tid  = threadIdx.x;
    const int wid  = tid >> 5;
    const int wm   = wid >> 2;
    const int wn   = wid & 3;

    wmma::fragment<wmma::accumulator, 16, 16, 16, float> c0, c1;
    wmma::fill_fragment(c0, 0.f);
    wmma::fill_fragment(c1, 0.f);

    const int  lr = tid >> 2;
    const int  lq = (tid & 3) * 8;
    const bool av = (m0 + lr) < NN;
    const float* arow = X + (size_t)(m0 + lr) * DD + lq;
    const float* brow = W + (size_t)(n0 + lr) * DD + lq;

    auto stage = [&](int buf, float4 a0, float4 a1, float4 b0, float4 b1) {
        __nv_bfloat16* Ah = (__nv_bfloat16*)smem_raw + buf * BUF_ELEMS;
        __nv_bfloat16* Al = Ah + 64 * A_LDM;
        __nv_bfloat16* Bh = Al + 64 * A_LDM;
        __nv_bfloat16* Bl = Bh + 64 * A_LDM;
        float va[8] = {a0.x, a0.y, a0.z, a0.w, a1.x, a1.y, a1.z, a1.w};
        float vb[8] = {b0.x, b0.y, b0.z, b0.w, b1.x, b1.y, b1.z, b1.w};
        __nv_bfloat16 hi[8], lo[8];
#pragma unroll
        for (int e = 0; e < 8; e++) {
            hi[e] = __float2bfloat16(va[e]);
            lo[e] = __float2bfloat16(va[e] - __bfloat162float(hi[e]));
        }
        *(uint4*)(Ah + lr * A_LDM + lq) = *(uint4*)hi;
        *(uint4*)(Al + lr * A_LDM + lq) = *(uint4*)lo;
#pragma unroll
        for (int e = 0; e < 8; e++) {
            hi[e] = __float2bfloat16(vb[e]);
            lo[e] = __float2bfloat16(vb[e] - __bfloat162float(hi[e]));
        }
        *(uint4*)(Bh + lr * A_LDM + lq) = *(uint4*)hi;
        *(uint4*)(Bl + lr * A_LDM + lq) = *(uint4*)lo;
    };

    {
        float4 a0 = av ? *(const float4*)(arow)     : make_float4(0, 0, 0, 0);
        float4 a1 = av ? *(const float4*)(arow + 4) : make_float4(0, 0, 0, 0);
        float4 b0 = *(const float4*)(brow);
        float4 b1 = *(const float4*)(brow + 4);
        stage(0, a0, a1, b0, b1);
    }
    __syncthreads();

    const int NCHUNK = DD / 32;
    for (int kc = 0; kc < NCHUNK; kc++) {
        const int cur = kc & 1;

        float4 a0, a1, b0, b1;
        const bool more = (kc + 1 < NCHUNK);
        if (more) {
            const int kb = (kc + 1) * 32;
            a0 = av ? *(const float4*)(arow + kb)     : make_float4(0, 0, 0, 0);
            a1 = av ? *(const float4*)(arow + kb + 4) : make_float4(0, 0, 0, 0);
            b0 = *(const float4*)(brow + kb);
            b1 = *(const float4*)(brow + kb + 4);
        }

        {
            __nv_bfloat16* Ah = (__nv_bfloat16*)smem_raw + cur * BUF_ELEMS;
            __nv_bfloat16* Al = Ah + 64 * A_LDM;
            __nv_bfloat16* Bh = Al + 64 * A_LDM;
            __nv_bfloat16* Bl = Bh + 64 * A_LDM;
#pragma unroll
            for (int ks = 0; ks < 2; ks++) {
                const int kk = ks * 16;
                wmma::fragment<wmma::matrix_b, 16, 16, 16, __nv_bfloat16, wmma::col_major> fbh, fbl;
                wmma::load_matrix_sync(fbh, Bh + (wn * 16) * A_LDM + kk, A_LDM);
                wmma::load_matrix_sync(fbl, Bl + (wn * 16) * A_LDM + kk, A_LDM);

                wmma::fragment<wmma::matrix_a, 16, 16, 16, __nv_bfloat16, wmma::row_major> fah, fal;
                wmma::load_matrix_sync(fah, Ah + (wm * 32) * A_LDM + kk, A_LDM);
                wmma::load_matrix_sync(fal, Al + (wm * 32) * A_LDM + kk, A_LDM);
                wmma::mma_sync(c0, fah, fbh, c0);
                wmma::mma_sync(c0, fah, fbl, c0);
                wmma::mma_sync(c0, fal, fbh, c0);
                wmma::load_matrix_sync(fah, Ah + (wm * 32 + 16) * A_LDM + kk, A_LDM);
                wmma::load_matrix_sync(fal, Al + (wm * 32 + 16) * A_LDM + kk, A_LDM);
                wmma::mma_sync(c1, fah, fbh, c1);
                wmma::mma_sync(c1, fah, fbl, c1);
                wmma::mma_sync(c1, fal, fbh, c1);
            }
        }

        if (more) stage(cur ^ 1, a0, a1, b0, b1);
        __syncthreads();
    }

    float* Cs = (float*)smem_raw;
    wmma::store_matrix_sync(Cs + (wm * 32) * C_LDM + wn * 16, c0, C_LDM, wmma::mem_row_major);
    wmma::store_matrix_sync(Cs + (wm * 32 + 16) * C_LDM + wn * 16, c1, C_LDM, wmma::mem_row_major);
    __syncthreads();

    const int m = m0 + lr;
    if (m < NN) {
        const int cb = (tid & 3) * 16;
        float* orow = O + (size_t)m * DD + n0 + cb;
        const float* bp = b + n0 + cb;
#pragma unroll
        for (int c4 = 0; c4 < 16; c4 += 4) {
            float4 vv = *(float4*)&Cs[lr * C_LDM + cb + c4];
            float4 bb = *(const float4*)(bp + c4);
            vv.x += bb.x; vv.y += bb.y; vv.z += bb.z; vv.w += bb.w;
            *(float4*)(orow + c4) = vv;
        }
    }
}

// ---------------------------------------------------------------------------
// FUSED score + segment-softmax + aggregation.
// grid = (26 i-tiles of 8 rows, 8 heads), 256 threads (8 warps).
// Warp w owns destination row i = i0+w for the whole kernel.
//   Phase A: S[w][j] = 0.4 * sum_c att|xl_j + xr_i|   (xl streamed in chunks)
//            AL_s[j] = 0.6 * sum_c att*xl_j           (computed per chunk)
//   Phase B: alpha[w][j] = segment softmax of S + AL (in place, count-weighted)
//   Phase C: OUT[i] = sum_j alpha * xl_j + bias (+ReLU)
// ---------------------------------------------------------------------------
__global__ void __launch_bounds__(256) k_fused(const float* __restrict__ att,
                                               const float* __restrict__ bias,
                                               int relu, int dst_sel) {
    float*    OUT  = dst_sel ? g_H2 : g_H;
    const int h    = blockIdx.y;
    const int i0   = blockIdx.x * 8;
    const int tid  = threadIdx.x;
    const int warp = tid >> 5;
    const int lane = tid & 31;
    const int i    = i0 + warp;

    __shared__ float4 xr_s[8][32];     // xr rows for this i-tile      (4 KB)
    __shared__ float  S_s[8][NPJ];     // scores -> alphas in place    (7 KB)
    __shared__ float  AL_s[NPJ];       //                              (0.9 KB)
    __shared__ float4 xs[32][32];      // xl chunk staging             (16 KB)

    // load xr rows (8 rows x 128 ch = 256 float4, one per thread)
    {
        int row = tid >> 5, cq = tid & 31;
        int ii = i0 + row;
        xr_s[row][cq] = (ii < NN)
            ? *(const float4*)(g_XR + (size_t)ii * DD + (h << 7) + (cq << 2))
            : make_float4(0, 0, 0, 0);
    }
    const float4 a4 = *(const float4*)(att + (h << 7) + (lane << 2));
    __syncthreads();
    const float4 rx = xr_s[warp][lane];

    // ---------------- Phase A: scores ----------------
    for (int jc = 0; jc < NN; jc += 32) {
        __syncthreads();   // previous chunk fully consumed
        for (int idx = tid; idx < 1024; idx += 256) {
            int jj = idx >> 5, cq = idx & 31;
            int j  = jc + jj;
            xs[jj][cq] = (j < NN)
                ? *(const float4*)(g_XL + (size_t)j * DD + (h << 7) + (cq << 2))
                : make_float4(0, 0, 0, 0);
        }
        __syncthreads();

        // AL for this chunk: 4 j per warp
#pragma unroll
        for (int q = 0; q < 4; q++) {
            const int jl = warp * 4 + q;
            float4 x = xs[jl][lane];
            float p = a4.x * x.x;
            p = fmaf(a4.y, x.y, p);
            p = fmaf(a4.z, x.z, p);
            p = fmaf(a4.w, x.w, p);
#pragma unroll
            for (int o = 16; o; o >>= 1) p += __shfl_xor_sync(0xffffffffu, p, o);
            if (lane == 0) AL_s[jc + jl] = 0.6f * p;
        }

        // scores for 32 j against this warp's row
#pragma unroll 4
        for (int jj = 0; jj < 32; jj++) {
            float4 x = xs[jj][lane];
            float t, p = 0.f;
            t = x.x + rx.x; p = fmaf(a4.x, fabsf(t), p);
            t = x.y + rx.y; p = fmaf(a4.y, fabsf(t), p);
            t = x.z + rx.z; p = fmaf(a4.z, fabsf(t), p);
            t = x.w + rx.w; p = fmaf(a4.w, fabsf(t), p);
#pragma unroll
            for (int o = 16; o; o >>= 1) p += __shfl_xor_sync(0xffffffffu, p, o);
            if (lane == 0) S_s[warp][jc + jj] = 0.4f * p;
        }
    }
    __syncthreads();

    // ---------------- Phase B: segment softmax ----------------
    if (i < NN) {
        const int* crow = g_cnt + i * NPJ;
        float sv[7], cv[7];
        float mx = -FLT_MAX;
#pragma unroll
        for (int t = 0; t < 7; t++) {
            int j = lane + t * 32;
            int c = crow[j];
            float s = (c > 0) ? S_s[warp][j] + AL_s[j] : -1e30f;
            sv[t] = s; cv[t] = (float)c;
            mx = fmaxf(mx, s);
        }
#pragma unroll
        for (int o = 16; o; o >>= 1) mx = fmaxf(mx, __shfl_xor_sync(0xffffffffu, mx, o));
        float ds = 0.f;
#pragma unroll
        for (int t = 0; t < 7; t++) ds += cv[t] * __expf(sv[t] - mx);
#pragma unroll
        for (int o = 16; o; o >>= 1) ds += __shfl_xor_sync(0xffffffffu, ds, o);
        float inv = 1.f / (ds + 1e-16f);
#pragma unroll
        for (int t = 0; t < 7; t++)
            S_s[warp][lane + t * 32] = cv[t] * __expf(sv[t] - mx) * inv;
    } else {
        for (int j = lane; j < NPJ; j += 32) S_s[warp][j] = 0.f;
    }

    // ---------------- Phase C: aggregation ----------------
    float4 acc = make_float4(0, 0, 0, 0);
    for (int jc = 0; jc < NN; jc += 32) {
        __syncthreads();
        for (int idx = tid; idx < 1024; idx += 256) {
            int jj = idx >> 5, cq = idx & 31;
            int j  = jc + jj;
            xs[jj][cq] = (j < NN)
                ? *(const float4*)(g_XL + (size_t)j * DD + (h << 7) + (cq << 2))
                : make_float4(0, 0, 0, 0);
        }
        __syncthreads();
#pragma unroll
        for (int jj = 0; jj < 32; jj++) {
            float  a = S_s[warp][jc + jj];
            float4 x = xs[jj][lane];
            acc.x = fmaf(a, x.x, acc.x);
            acc.y = fmaf(a, x.y, acc.y);
            acc.z = fmaf(a, x.z, acc.z);
            acc.w = fmaf(a, x.w, acc.w);
        }
    }

    if (i < NN) {
        float4 bb = *(const float4*)(bias + (h << 7) + (lane << 2));
        float4 o;
        o.x = acc.x + bb.x; o.y = acc.y + bb.y;
        o.z = acc.z + bb.z; o.w = acc.w + bb.w;
        if (relu) {
            o.x = fmaxf(o.x, 0.f); o.y = fmaxf(o.y, 0.f);
            o.z = fmaxf(o.z, 0.f); o.w = fmaxf(o.w, 0.f);
        }
        *(float4*)(OUT + (size_t)i * DD + (h << 7) + (lane << 2)) = o;
    }
}

// ---------------------------------------------------------------------------
// Pooling (parallel over 8 blocks): avg[d] = sum_i w_i * H2[i][d]
// ---------------------------------------------------------------------------
__global__ void k_pool() {
    int d = blockIdx.x * blockDim.x + threadIdx.x;
    float s = 0.f;
#pragma unroll 8
    for (int i = 0; i < NN - 1; i++) s += g_H2[i * DD + d];
    s = s * (1.f / 300.f) + g_H2[(NN - 1) * DD + d] * (1.f / 3.f);
    g_avg[d] = s;
}

// ---------------------------------------------------------------------------
// Classifier: out[c] = avg . clfW[c] + clfb[c]
// ---------------------------------------------------------------------------
__global__ void k_clf(const float* __restrict__ W, const float* __restrict__ b,
                      float* __restrict__ out) {
    __shared__ float red0[8], red1[8];
    int tid = threadIdx.x;
    float p0 = 0.f, p1 = 0.f;
    for (int d = tid; d < DD; d += 256) {
        float a = g_avg[d];
        p0 = fmaf(a, W[d], p0);
        p1 = fmaf(a, W[DD + d], p1);
    }
    for (int o = 16; o; o >>= 1) {
        p0 += __shfl_xor_sync(0xffffffffu, p0, o);
        p1 += __shfl_xor_sync(0xffffffffu, p1, o);
    }
    if ((tid & 31) == 0) { red0[tid >> 5] = p0; red1[tid >> 5] = p1; }
    __syncthreads();
    if (tid == 0) {
        float s0 = 0.f, s1 = 0.f;
        for (int w = 0; w < 8; w++) { s0 += red0[w]; s1 += red1[w]; }
        out[0] = s0 + b[0];
        out[1] = s1 + b[1];
    }
}

// ---------------------------------------------------------------------------
extern "C" void kernel_launch(void* const* d_in, const int* in_sizes, int n_in,
                              void* d_out, int out_size) {
    const float* x     = (const float*)d_in[0];
    const int*   ebuf  = (const int*)  d_in[1];
    const float* W1l   = (const float*)d_in[2];
    const float* b1l   = (const float*)d_in[3];
    const float* W1r   = (const float*)d_in[4];
    const float* b1r   = (const float*)d_in[5];
    const float* att1  = (const float*)d_in[6];
    const float* bias1 = (const float*)d_in[7];
    const float* W2l   = (const float*)d_in[8];
    const float* b2l   = (const float*)d_in[9];
    const float* W2r   = (const float*)d_in[10];
    const float* b2r   = (const float*)d_in[11];
    const float* att2  = (const float*)d_in[12];
    const float* bias2 = (const float*)d_in[13];
    const float* clfW  = (const float*)d_in[14];
    const float* clfb  = (const float*)d_in[15];
    float* out = (float*)d_out;

    k_init <<<(NN * NPJ + 255) / 256, 256>>>(ebuf);
    k_count<<<(EE + 255) / 256, 256>>>(ebuf);

    dim3 gg(4, 16, 2);          // m-tiles x n-tiles x {l,r}
    dim3 gf(26, HH);            // i-tiles x heads

    // layer 1
    k_gemm_mma<<<gg, 256>>>(x, W1l, b1l, W1r, b1r);
    k_fused   <<<gf, 256>>>(att1, bias1, /*relu=*/1, /*dst=*/0);

    // layer 2
    k_gemm_mma<<<gg, 256>>>(nullptr, W2l, b2l, W2r, b2r);
    k_fused   <<<gf, 256>>>(att2, bias2, /*relu=*/0, /*dst=*/1);

    // pooling + classifier
    k_pool<<<8, 128>>>();
    k_clf <<<1, 256>>>(clfW, clfb, out);
}

// round 7
// speedup vs baseline: 1.2557x; 1.2557x over previous
#include <cuda_runtime.h>
#include <cuda_bf16.h>
#include <mma.h>
#include <math.h>
#include <float.h>
#include <stdint.h>

using namespace nvcuda;

// ----------------------------------------------------------------------------
// GATv2 x2 + mean-pool + classifier, dense-pair formulation.
// N=201, E=40200 (+201 self loops), D=1024 = 8 heads x 128 ch.
// GEMMs: WMMA bf16 hi/lo split x3 (tcgen05 unavailable: harness targets sm_103).
// ----------------------------------------------------------------------------

#define NN   201
#define EE   40200
#define DD   1024
#define HH   8
#define CC   128
#define NPJ  224
#define NPAD 204

// -------- scratch (device globals; no allocation allowed) -------------------
__device__ __align__(16) float g_XL[NPAD * DD];
__device__ __align__(16) float g_XR[NPAD * DD];
__device__ __align__(16) float g_H [NPAD * DD];
__device__ __align__(16) float g_H2[NPAD * DD];
__device__ __align__(16) float g_S [HH * NN * NPJ];
__device__ int   g_cnt[NN * NPJ];     // statically zero; re-zeroed by k_pool
__device__ __align__(16) float g_avg[DD];

// ---------------------------------------------------------------------------
// Edge count: detects int32/int64 stride per block, counts edges + self loops.
// g_cnt must be all-zero on entry (static init first call; k_pool re-zeroes).
// ---------------------------------------------------------------------------
__global__ void k_count(const int* __restrict__ eb) {
    __shared__ int st_s;
    if (threadIdx.x == 0) {
        int st = 2;  // int64: odd words are high halves (zero for values < 2^31)
        for (int e = 0; e < 64; e++)
            if (eb[2 * e + 1] != 0) { st = 1; break; }
        st_s = st;
    }
    __syncthreads();
    const int st = st_s;
    int e = blockIdx.x * blockDim.x + threadIdx.x;
    if (e < EE) {
        int src = eb[e * st];
        int dst = eb[(EE + e) * st];
        atomicAdd(&g_cnt[dst * NPJ + src], 1);
    } else if (e < EE + NN) {
        int v = e - EE;                     // self loop
        atomicAdd(&g_cnt[v * NPJ + v], 1);
    }
}

// ---------------------------------------------------------------------------
// WMMA bf16 GEMM, double-buffered: O[m][n] = sum_k X[m][k]*W[n][k] + b[n]
// CTA tile 64x64, K chunk 32, 2-deep smem pipeline, hi/lo split x3.
// grid = (4 m-tiles, 16 n-tiles, 2 sides); 256 threads (8 warps, 32x16 each).
// ---------------------------------------------------------------------------
#define A_LDM 40           // 32 k + 8 pad (bf16)
#define C_LDM 72           // 64 n + 8 pad (fp32)
#define BUF_ELEMS (4 * 64 * A_LDM)

__global__ void __launch_bounds__(256) k_gemm_mma(
    const float* __restrict__ Xin,
    const float* __restrict__ Wl, const float* __restrict__ bl,
    const float* __restrict__ Wr, const float* __restrict__ br)
{
    __shared__ __align__(16) char smem_raw[2 * BUF_ELEMS * 2];

    const float* X = Xin ? Xin : g_H;
    const int side = blockIdx.z;
    const float* W = side ? Wr : Wl;
    const float* b = side ? br : bl;
    float*       O = side ? g_XR : g_XL;
    const int m0 = blockIdx.x * 64;
    const int n0 = blockIdx.y * 64;

    const int tid  = threadIdx.x;
    const int wid  = tid >> 5;
    const int wm   = wid >> 2;
    const int wn   = wid & 3;

    wmma::fragment<wmma::accumulator, 16, 16, 16, float> c0, c1;
    wmma::fill_fragment(c0, 0.f);
    wmma::fill_fragment(c1, 0.f);

    const int  lr = tid >> 2;
    const int  lq = (tid & 3) * 8;
    const bool av = (m0 + lr) < NN;
    const float* arow = X + (size_t)(m0 + lr) * DD + lq;
    const float* brow = W + (size_t)(n0 + lr) * DD + lq;

    auto stage = [&](int buf, float4 a0, float4 a1, float4 b0, float4 b1) {
        __nv_bfloat16* Ah = (__nv_bfloat16*)smem_raw + buf * BUF_ELEMS;
        __nv_bfloat16* Al = Ah + 64 * A_LDM;
        __nv_bfloat16* Bh = Al + 64 * A_LDM;
        __nv_bfloat16* Bl = Bh + 64 * A_LDM;
        float va[8] = {a0.x, a0.y, a0.z, a0.w, a1.x, a1.y, a1.z, a1.w};
        float vb[8] = {b0.x, b0.y, b0.z, b0.w, b1.x, b1.y, b1.z, b1.w};
        __nv_bfloat16 hi[8], lo[8];
#pragma unroll
        for (int e = 0; e < 8; e++) {
            hi[e] = __float2bfloat16(va[e]);
            lo[e] = __float2bfloat16(va[e] - __bfloat162float(hi[e]));
        }
        *(uint4*)(Ah + lr * A_LDM + lq) = *(uint4*)hi;
        *(uint4*)(Al + lr * A_LDM + lq) = *(uint4*)lo;
#pragma unroll
        for (int e = 0; e < 8; e++) {
            hi[e] = __float2bfloat16(vb[e]);
            lo[e] = __float2bfloat16(vb[e] - __bfloat162float(hi[e]));
        }
        *(uint4*)(Bh + lr * A_LDM + lq) = *(uint4*)hi;
        *(uint4*)(Bl + lr * A_LDM + lq) = *(uint4*)lo;
    };

    {
        float4 a0 = av ? *(const float4*)(arow)     : make_float4(0, 0, 0, 0);
        float4 a1 = av ? *(const float4*)(arow + 4) : make_float4(0, 0, 0, 0);
        float4 b0 = *(const float4*)(brow);
        float4 b1 = *(const float4*)(brow + 4);
        stage(0, a0, a1, b0, b1);
    }
    __syncthreads();

    const int NCHUNK = DD / 32;
    for (int kc = 0; kc < NCHUNK; kc++) {
        const int cur = kc & 1;

        float4 a0, a1, b0, b1;
        const bool more = (kc + 1 < NCHUNK);
        if (more) {
            const int kb = (kc + 1) * 32;
            a0 = av ? *(const float4*)(arow + kb)     : make_float4(0, 0, 0, 0);
            a1 = av ? *(const float4*)(arow + kb + 4) : make_float4(0, 0, 0, 0);
            b0 = *(const float4*)(brow + kb);
            b1 = *(const float4*)(brow + kb + 4);
        }

        {
            __nv_bfloat16* Ah = (__nv_bfloat16*)smem_raw + cur * BUF_ELEMS;
            __nv_bfloat16* Al = Ah + 64 * A_LDM;
            __nv_bfloat16* Bh = Al + 64 * A_LDM;
            __nv_bfloat16* Bl = Bh + 64 * A_LDM;
#pragma unroll
            for (int ks = 0; ks < 2; ks++) {
                const int kk = ks * 16;
                wmma::fragment<wmma::matrix_b, 16, 16, 16, __nv_bfloat16, wmma::col_major> fbh, fbl;
                wmma::load_matrix_sync(fbh, Bh + (wn * 16) * A_LDM + kk, A_LDM);
                wmma::load_matrix_sync(fbl, Bl + (wn * 16) * A_LDM + kk, A_LDM);

                wmma::fragment<wmma::matrix_a, 16, 16, 16, __nv_bfloat16, wmma::row_major> fah, fal;
                wmma::load_matrix_sync(fah, Ah + (wm * 32) * A_LDM + kk, A_LDM);
                wmma::load_matrix_sync(fal, Al + (wm * 32) * A_LDM + kk, A_LDM);
                wmma::mma_sync(c0, fah, fbh, c0);
                wmma::mma_sync(c0, fah, fbl, c0);
                wmma::mma_sync(c0, fal, fbh, c0);
                wmma::load_matrix_sync(fah, Ah + (wm * 32 + 16) * A_LDM + kk, A_LDM);
                wmma::load_matrix_sync(fal, Al + (wm * 32 + 16) * A_LDM + kk, A_LDM);
                wmma::mma_sync(c1, fah, fbh, c1);
                wmma::mma_sync(c1, fah, fbl, c1);
                wmma::mma_sync(c1, fal, fbh, c1);
            }
        }

        if (more) stage(cur ^ 1, a0, a1, b0, b1);
        __syncthreads();
    }

    float* Cs = (float*)smem_raw;
    wmma::store_matrix_sync(Cs + (wm * 32) * C_LDM + wn * 16, c0, C_LDM, wmma::mem_row_major);
    wmma::store_matrix_sync(Cs + (wm * 32 + 16) * C_LDM + wn * 16, c1, C_LDM, wmma::mem_row_major);
    __syncthreads();

    const int m = m0 + lr;
    if (m < NN) {
        const int cb = (tid & 3) * 16;
        float* orow = O + (size_t)m * DD + n0 + cb;
        const float* bp = b + n0 + cb;
#pragma unroll
        for (int c4 = 0; c4 < 16; c4 += 4) {
            float4 vv = *(float4*)&Cs[lr * C_LDM + cb + c4];
            float4 bb = *(const float4*)(bp + c4);
            vv.x += bb.x; vv.y += bb.y; vv.z += bb.z; vv.w += bb.w;
            *(float4*)(orow + c4) = vv;
        }
    }
}

// ---------------------------------------------------------------------------
// Dense pairwise scores, 32i x 64j tiles, 128 threads, 2x8 microtile.
//   S[h,i,j] = 0.4 * sum_c att|xl_j + xr_i| + 0.6*AL[j]   (AR term cancels)
// grid = (7 i-tiles, 4 j-tiles, 8 heads) = 224 blocks.
// ---------------------------------------------------------------------------
__global__ void __launch_bounds__(128) k_score(const float* __restrict__ att) {
    const int h   = blockIdx.z;
    const int i0  = blockIdx.x * 32;
    const int j0  = blockIdx.y * 64;
    const int tid = threadIdx.x;
    const int tx  = tid & 7;          // -> 8 j columns
    const int ty  = tid >> 3;         // -> 2 i rows

    __shared__ __align__(16) float att_s[CC];
    __shared__ float AL_s[64];
    __shared__ float alp[64][2];
    __shared__ float As[16][32];      // xr chunk [k][i]
    __shared__ float Bs[16][64];      // xl chunk [k][j]

    if (tid < 32) *(float4*)&att_s[tid * 4] = *(const float4*)(att + h * CC + tid * 4);
    __syncthreads();

    // AL[j]: 2 threads per j, 64 channels each
    {
        int jj = tid >> 1, part = tid & 1;
        int j  = j0 + jj;
        float s = 0.f;
        if (j < NN) {
            const float4* xp4 = (const float4*)(g_XL + (size_t)j * DD + h * CC + part * 64);
#pragma unroll
            for (int q = 0; q < 16; q++) {
                float4 xv = xp4[q];
                const float* ap = att_s + part * 64 + q * 4;
                s = fmaf(ap[0], xv.x, s);
                s = fmaf(ap[1], xv.y, s);
                s = fmaf(ap[2], xv.z, s);
                s = fmaf(ap[3], xv.w, s);
            }
        }
        alp[jj][part] = s;
    }
    __syncthreads();
    if (tid < 64) AL_s[tid] = alp[tid][0] + alp[tid][1];
    __syncthreads();

    // staging thread mapping
    const int  ar = tid & 31;             // A row (i)
    const int  akq = (tid >> 5) << 2;     // A k-quad: 0,4,8,12
    const int  br = tid & 63;             // B row (j)
    const int  bkq = (tid >> 6) << 3;     // B k-octet: 0,8
    const bool ivv = (i0 + ar) < NN;
    const bool jvv = (j0 + br) < NN;
    const float* xrp = g_XR + (size_t)(i0 + ar) * DD + h * CC;
    const float* xlp = g_XL + (size_t)(j0 + br) * DD + h * CC;

    float acc[2][8];
#pragma unroll
    for (int i = 0; i < 2; i++)
#pragma unroll
        for (int j = 0; j < 8; j++) acc[i][j] = 0.f;

    float4 ra  = ivv ? *(const float4*)(xrp + akq)     : make_float4(0, 0, 0, 0);
    float4 rb0 = jvv ? *(const float4*)(xlp + bkq)     : make_float4(0, 0, 0, 0);
    float4 rb1 = jvv ? *(const float4*)(xlp + bkq + 4) : make_float4(0, 0, 0, 0);

    for (int k0 = 0; k0 < CC; k0 += 16) {
        As[akq + 0][ar] = ra.x; As[akq + 1][ar] = ra.y;
        As[akq + 2][ar] = ra.z; As[akq + 3][ar] = ra.w;
        Bs[bkq + 0][br] = rb0.x; Bs[bkq + 1][br] = rb0.y;
        Bs[bkq + 2][br] = rb0.z; Bs[bkq + 3][br] = rb0.w;
        Bs[bkq + 4][br] = rb1.x; Bs[bkq + 5][br] = rb1.y;
        Bs[bkq + 6][br] = rb1.z; Bs[bkq + 7][br] = rb1.w;
        __syncthreads();

        if (k0 + 16 < CC) {
            ra  = ivv ? *(const float4*)(xrp + k0 + 16 + akq)     : make_float4(0, 0, 0, 0);
            rb0 = jvv ? *(const float4*)(xlp + k0 + 16 + bkq)     : make_float4(0, 0, 0, 0);
            rb1 = jvv ? *(const float4*)(xlp + k0 + 16 + bkq + 4) : make_float4(0, 0, 0, 0);
        }

#pragma unroll
        for (int k = 0; k < 16; k++) {
            float a0 = As[k][ty * 2 + 0];
            float a1 = As[k][ty * 2 + 1];
            float4 v0 = *(const float4*)&Bs[k][tx * 8];
            float4 v1 = *(const float4*)&Bs[k][tx * 8 + 4];
            float bv[8] = {v0.x, v0.y, v0.z, v0.w, v1.x, v1.y, v1.z, v1.w};
            float ac = att_s[k0 + k];
#pragma unroll
            for (int j = 0; j < 8; j++) {
                float t0 = a0 + bv[j];
                float t1 = a1 + bv[j];
                acc[0][j] = fmaf(ac, fabsf(t0), acc[0][j]);
                acc[1][j] = fmaf(ac, fabsf(t1), acc[1][j]);
            }
        }
        __syncthreads();
    }

#pragma unroll
    for (int ii = 0; ii < 2; ii++) {
        int i = i0 + ty * 2 + ii;
        if (i >= NN) continue;
        float* row = g_S + (size_t)(h * NN + i) * NPJ;
#pragma unroll
        for (int jj = 0; jj < 8; jj++) {
            int j = j0 + tx * 8 + jj;
            if (j < NN)
                row[j] = fmaf(0.4f, acc[ii][jj], 0.6f * AL_s[tx * 8 + jj]);
        }
    }
}

// ---------------------------------------------------------------------------
// Fused segment-softmax + aggregation.
// Block = (i-tile of 8, head). Warp w owns destination row i0+w.
// ---------------------------------------------------------------------------
__global__ void __launch_bounds__(256) k_agg(const float* __restrict__ bias,
                                             int relu, int dst_sel) {
    float*    OUT  = dst_sel ? g_H2 : g_H;
    const int h    = blockIdx.y;
    const int i0   = blockIdx.x * 8;
    const int warp = threadIdx.x >> 5;
    const int lane = threadIdx.x & 31;

    __shared__ float  al[8][NPJ];
    __shared__ float4 xs[32][32];

    {
        int i = i0 + warp;
        if (i < NN) {
            const float* srow = g_S + (size_t)(h * NN + i) * NPJ;
            const int*   crow = g_cnt + i * NPJ;
            float sv[7], cv[7];
            float mx = -FLT_MAX;
#pragma unroll
            for (int t = 0; t < 7; t++) {
                int j = lane + t * 32;
                int c = (j < NN) ? crow[j] : 0;
                float s = (c > 0) ? srow[j] : -1e30f;
                sv[t] = s; cv[t] = (float)c;
                mx = fmaxf(mx, s);
            }
            for (int o = 16; o; o >>= 1) mx = fmaxf(mx, __shfl_xor_sync(0xffffffffu, mx, o));
            float ds = 0.f;
#pragma unroll
            for (int t = 0; t < 7; t++) ds += cv[t] * __expf(sv[t] - mx);
            for (int o = 16; o; o >>= 1) ds += __shfl_xor_sync(0xffffffffu, ds, o);
            float inv = 1.f / (ds + 1e-16f);
#pragma unroll
            for (int t = 0; t < 7; t++)
                al[warp][lane + t * 32] = cv[t] * __expf(sv[t] - mx) * inv;
        } else {
            for (int j = lane; j < NPJ; j += 32) al[warp][j] = 0.f;
        }
    }

    float4 acc = make_float4(0, 0, 0, 0);
    for (int j0 = 0; j0 < NN; j0 += 32) {
        __syncthreads();
        for (int idx = threadIdx.x; idx < 1024; idx += 256) {
            int jj = idx >> 5, cq = idx & 31;
            int j  = j0 + jj;
            xs[jj][cq] = (j < NN)
                ? *(const float4*)(g_XL + (size_t)j * DD + (h << 7) + (cq << 2))
                : make_float4(0, 0, 0, 0);
        }
        __syncthreads();
#pragma unroll
        for (int jj = 0; jj < 32; jj++) {
            float  a = al[warp][j0 + jj];
            float4 x = xs[jj][lane];
            acc.x = fmaf(a, x.x, acc.x);
            acc.y = fmaf(a, x.y, acc.y);
            acc.z = fmaf(a, x.z, acc.z);
            acc.w = fmaf(a, x.w, acc.w);
        }
    }

    int i = i0 + warp;
    if (i < NN) {
        float4 bb = *(const float4*)(bias + (h << 7) + (lane << 2));
        float4 o;
        o.x = acc.x + bb.x; o.y = acc.y + bb.y;
        o.z = acc.z + bb.z; o.w = acc.w + bb.w;
        if (relu) {
            o.x = fmaxf(o.x, 0.f); o.y = fmaxf(o.y, 0.f);
            o.z = fmaxf(o.z, 0.f); o.w = fmaxf(o.w, 0.f);
        }
        *(float4*)(OUT + (size_t)i * DD + (h << 7) + (lane << 2)) = o;
    }
}

// ---------------------------------------------------------------------------
// Pooling (8 blocks x 128): avg[d] = sum_i w_i * H2[i][d].
// Also re-zeroes g_cnt for the next graph replay.
// ---------------------------------------------------------------------------
__global__ void k_pool() {
    int d = blockIdx.x * blockDim.x + threadIdx.x;
    float s = 0.f;
#pragma unroll 8
    for (int i = 0; i < NN - 1; i++) s += g_H2[i * DD + d];
    s = s * (1.f / 300.f) + g_H2[(NN - 1) * DD + d] * (1.f / 3.f);
    g_avg[d] = s;
    // reset count matrix for next call (graph replay)
    for (int idx = d; idx < NN * NPJ; idx += 1024) g_cnt[idx] = 0;
}

// ---------------------------------------------------------------------------
// Classifier: out[c] = avg . clfW[c] + clfb[c]
// ---------------------------------------------------------------------------
__global__ void k_clf(const float* __restrict__ W, const float* __restrict__ b,
                      float* __restrict__ out) {
    __shared__ float red0[8], red1[8];
    int tid = threadIdx.x;
    float p0 = 0.f, p1 = 0.f;
    for (int d = tid; d < DD; d += 256) {
        float a = g_avg[d];
        p0 = fmaf(a, W[d], p0);
        p1 = fmaf(a, W[DD + d], p1);
    }
    for (int o = 16; o; o >>= 1) {
        p0 += __shfl_xor_sync(0xffffffffu, p0, o);
        p1 += __shfl_xor_sync(0xffffffffu, p1, o);
    }
    if ((tid & 31) == 0) { red0[tid >> 5] = p0; red1[tid >> 5] = p1; }
    __syncthreads();
    if (tid == 0) {
        float s0 = 0.f, s1 = 0.f;
        for (int w = 0; w < 8; w++) { s0 += red0[w]; s1 += red1[w]; }
        out[0] = s0 + b[0];
        out[1] = s1 + b[1];
    }
}

// ---------------------------------------------------------------------------
extern "C" void kernel_launch(void* const* d_in, const int* in_sizes, int n_in,
                              void* d_out, int out_size) {
    const float* x     = (const float*)d_in[0];
    const int*   ebuf  = (const int*)  d_in[1];
    const float* W1l   = (const float*)d_in[2];
    const float* b1l   = (const float*)d_in[3];
    const float* W1r   = (const float*)d_in[4];
    const float* b1r   = (const float*)d_in[5];
    const float* att1  = (const float*)d_in[6];
    const float* bias1 = (const float*)d_in[7];
    const float* W2l   = (const float*)d_in[8];
    const float* b2l   = (const float*)d_in[9];
    const float* W2r   = (const float*)d_in[10];
    const float* b2r   = (const float*)d_in[11];
    const float* att2  = (const float*)d_in[12];
    const float* bias2 = (const float*)d_in[13];
    const float* clfW  = (const float*)d_in[14];
    const float* clfb  = (const float*)d_in[15];
    float* out = (float*)d_out;

    k_count<<<(EE + NN + 255) / 256, 256>>>(ebuf);

    dim3 gg(4, 16, 2);          // m-tiles x n-tiles x {l,r}
    dim3 gs(7, 4, HH);          // i-tiles x j-tiles x heads (224 blocks)

    // layer 1
    k_gemm_mma<<<gg, 256>>>(x, W1l, b1l, W1r, b1r);
    k_score   <<<gs, 128>>>(att1);
    k_agg     <<<dim3(26, HH), 256>>>(bias1, /*relu=*/1, /*dst=*/0);

    // layer 2
    k_gemm_mma<<<gg, 256>>>(nullptr, W2l, b2l, W2r, b2r);
    k_score   <<<gs, 128>>>(att2);
    k_agg     <<<dim3(26, HH), 256>>>(bias2, /*relu=*/0, /*dst=*/1);

    // pooling (+ g_cnt reset) and classifier
    k_pool<<<8, 128>>>();
    k_clf <<<1, 256>>>(clfW, clfb, out);
}

// round 8
// speedup vs baseline: 1.5240x; 1.2137x over previous
#include <cuda_runtime.h>
#include <cuda_bf16.h>
#include <mma.h>
#include <math.h>
#include <float.h>
#include <stdint.h>

using namespace nvcuda;

// ----------------------------------------------------------------------------
// GATv2 x2 + mean-pool + classifier, dense-pair formulation.
// N=201, E=40200 (+201 self loops), D=1024 = 8 heads x 128 ch.
// GEMMs: WMMA bf16 hi/lo split x3. Aggregation: alpha-normalize + fp32 GEMM.
// ----------------------------------------------------------------------------

#define NN   201
#define EE   40200
#define DD   1024
#define HH   8
#define CC   128
#define NPJ  224
#define NPAD 204

// -------- scratch (device globals; no allocation allowed) -------------------
__device__ __align__(16) float g_XL[NPAD * DD];
__device__ __align__(16) float g_XR[NPAD * DD];
__device__ __align__(16) float g_H [NPAD * DD];
__device__ __align__(16) float g_H2[NPAD * DD];
__device__ __align__(16) float g_S [HH * NN * NPJ];   // scores -> alphas (in place)
__device__ int   g_cnt[NN * NPJ];     // statically zero; re-zeroed by k_pool
__device__ __align__(16) float g_avg[DD];

// ---------------------------------------------------------------------------
// Edge count: detects int32/int64 stride per block, counts edges + self loops.
// ---------------------------------------------------------------------------
__global__ void k_count(const int* __restrict__ eb) {
    __shared__ int st_s;
    if (threadIdx.x == 0) {
        int st = 2;
        for (int e = 0; e < 64; e++)
            if (eb[2 * e + 1] != 0) { st = 1; break; }
        st_s = st;
    }
    __syncthreads();
    const int st = st_s;
    int e = blockIdx.x * blockDim.x + threadIdx.x;
    if (e < EE) {
        int src = eb[e * st];
        int dst = eb[(EE + e) * st];
        atomicAdd(&g_cnt[dst * NPJ + src], 1);
    } else if (e < EE + NN) {
        int v = e - EE;
        atomicAdd(&g_cnt[v * NPJ + v], 1);
    }
}

// ---------------------------------------------------------------------------
// WMMA bf16 GEMM, double-buffered: O[m][n] = sum_k X[m][k]*W[n][k] + b[n]
// ---------------------------------------------------------------------------
#define A_LDM 40
#define C_LDM 72
#define BUF_ELEMS (4 * 64 * A_LDM)

__global__ void __launch_bounds__(256) k_gemm_mma(
    const float* __restrict__ Xin,
    const float* __restrict__ Wl, const float* __restrict__ bl,
    const float* __restrict__ Wr, const float* __restrict__ br)
{
    __shared__ __align__(16) char smem_raw[2 * BUF_ELEMS * 2];

    const float* X = Xin ? Xin : g_H;
    const int side = blockIdx.z;
    const float* W = side ? Wr : Wl;
    const float* b = side ? br : bl;
    float*       O = side ? g_XR : g_XL;
    const int m0 = blockIdx.x * 64;
    const int n0 = blockIdx.y * 64;

    const int tid  = threadIdx.x;
    const int wid  = tid >> 5;
    const int wm   = wid >> 2;
    const int wn   = wid & 3;

    wmma::fragment<wmma::accumulator, 16, 16, 16, float> c0, c1;
    wmma::fill_fragment(c0, 0.f);
    wmma::fill_fragment(c1, 0.f);

    const int  lr = tid >> 2;
    const int  lq = (tid & 3) * 8;
    const bool av = (m0 + lr) < NN;
    const float* arow = X + (size_t)(m0 + lr) * DD + lq;
    const float* brow = W + (size_t)(n0 + lr) * DD + lq;

    auto stage = [&](int buf, float4 a0, float4 a1, float4 b0, float4 b1) {
        __nv_bfloat16* Ah = (__nv_bfloat16*)smem_raw + buf * BUF_ELEMS;
        __nv_bfloat16* Al = Ah + 64 * A_LDM;
        __nv_bfloat16* Bh = Al + 64 * A_LDM;
        __nv_bfloat16* Bl = Bh + 64 * A_LDM;
        float va[8] = {a0.x, a0.y, a0.z, a0.w, a1.x, a1.y, a1.z, a1.w};
        float vb[8] = {b0.x, b0.y, b0.z, b0.w, b1.x, b1.y, b1.z, b1.w};
        __nv_bfloat16 hi[8], lo[8];
#pragma unroll
        for (int e = 0; e < 8; e++) {
            hi[e] = __float2bfloat16(va[e]);
            lo[e] = __float2bfloat16(va[e] - __bfloat162float(hi[e]));
        }
        *(uint4*)(Ah + lr * A_LDM + lq) = *(uint4*)hi;
        *(uint4*)(Al + lr * A_LDM + lq) = *(uint4*)lo;
#pragma unroll
        for (int e = 0; e < 8; e++) {
            hi[e] = __float2bfloat16(vb[e]);
            lo[e] = __float2bfloat16(vb[e] - __bfloat162float(hi[e]));
        }
        *(uint4*)(Bh + lr * A_LDM + lq) = *(uint4*)hi;
        *(uint4*)(Bl + lr * A_LDM + lq) = *(uint4*)lo;
    };

    {
        float4 a0 = av ? *(const float4*)(arow)     : make_float4(0, 0, 0, 0);
        float4 a1 = av ? *(const float4*)(arow + 4) : make_float4(0, 0, 0, 0);
        float4 b0 = *(const float4*)(brow);
        float4 b1 = *(const float4*)(brow + 4);
        stage(0, a0, a1, b0, b1);
    }
    __syncthreads();

    const int NCHUNK = DD / 32;
    for (int kc = 0; kc < NCHUNK; kc++) {
        const int cur = kc & 1;

        float4 a0, a1, b0, b1;
        const bool more = (kc + 1 < NCHUNK);
        if (more) {
            const int kb = (kc + 1) * 32;
            a0 = av ? *(const float4*)(arow + kb)     : make_float4(0, 0, 0, 0);
            a1 = av ? *(const float4*)(arow + kb + 4) : make_float4(0, 0, 0, 0);
            b0 = *(const float4*)(brow + kb);
            b1 = *(const float4*)(brow + kb + 4);
        }

        {
            __nv_bfloat16* Ah = (__nv_bfloat16*)smem_raw + cur * BUF_ELEMS;
            __nv_bfloat16* Al = Ah + 64 * A_LDM;
            __nv_bfloat16* Bh = Al + 64 * A_LDM;
            __nv_bfloat16* Bl = Bh + 64 * A_LDM;
#pragma unroll
            for (int ks = 0; ks < 2; ks++) {
                const int kk = ks * 16;
                wmma::fragment<wmma::matrix_b, 16, 16, 16, __nv_bfloat16, wmma::col_major> fbh, fbl;
                wmma::load_matrix_sync(fbh, Bh + (wn * 16) * A_LDM + kk, A_LDM);
                wmma::load_matrix_sync(fbl, Bl + (wn * 16) * A_LDM + kk, A_LDM);

                wmma::fragment<wmma::matrix_a, 16, 16, 16, __nv_bfloat16, wmma::row_major> fah, fal;
                wmma::load_matrix_sync(fah, Ah + (wm * 32) * A_LDM + kk, A_LDM);
                wmma::load_matrix_sync(fal, Al + (wm * 32) * A_LDM + kk, A_LDM);
                wmma::mma_sync(c0, fah, fbh, c0);
                wmma::mma_sync(c0, fah, fbl, c0);
                wmma::mma_sync(c0, fal, fbh, c0);
                wmma::load_matrix_sync(fah, Ah + (wm * 32 + 16) * A_LDM + kk, A_LDM);
                wmma::load_matrix_sync(fal, Al + (wm * 32 + 16) * A_LDM + kk, A_LDM);
                wmma::mma_sync(c1, fah, fbh, c1);
                wmma::mma_sync(c1, fah, fbl, c1);
                wmma::mma_sync(c1, fal, fbh, c1);
            }
        }

        if (more) stage(cur ^ 1, a0, a1, b0, b1);
        __syncthreads();
    }

    float* Cs = (float*)smem_raw;
    wmma::store_matrix_sync(Cs + (wm * 32) * C_LDM + wn * 16, c0, C_LDM, wmma::mem_row_major);
    wmma::store_matrix_sync(Cs + (wm * 32 + 16) * C_LDM + wn * 16, c1, C_LDM, wmma::mem_row_major);
    __syncthreads();

    const int m = m0 + lr;
    if (m < NN) {
        const int cb = (tid & 3) * 16;
        float* orow = O + (size_t)m * DD + n0 + cb;
        const float* bp = b + n0 + cb;
#pragma unroll
        for (int c4 = 0; c4 < 16; c4 += 4) {
            float4 vv = *(float4*)&Cs[lr * C_LDM + cb + c4];
            float4 bb = *(const float4*)(bp + c4);
            vv.x += bb.x; vv.y += bb.y; vv.z += bb.z; vv.w += bb.w;
            *(float4*)(orow + c4) = vv;
        }
    }
}

// ---------------------------------------------------------------------------
// Dense pairwise scores, 32x32 tiles / 128 threads (R5 version, measured 14.9us)
//   S[h,i,j] = 0.4 * sum_c att|xl_j + xr_i| + 0.6*AL[j]   (AR term cancels)
// grid = (7, 7, 8) = 392 blocks; microtile 2i x 4j.
// ---------------------------------------------------------------------------
__global__ void __launch_bounds__(128) k_score(const float* __restrict__ att) {
    const int h   = blockIdx.z;
    const int i0  = blockIdx.x * 32;
    const int j0  = blockIdx.y * 32;
    const int tid = threadIdx.x;
    const int tx  = tid & 7;
    const int ty  = tid >> 3;
    const int lrow = tid >> 2;
    const int lq   = (tid & 3) << 2;

    __shared__ __align__(16) float att_s[CC];
    __shared__ float AL_s[32];
    __shared__ float alp[32][4];
    __shared__ float As[16][32];
    __shared__ float Bs[16][32];

    if (tid < 32) *(float4*)&att_s[tid * 4] = *(const float4*)(att + h * CC + tid * 4);
    __syncthreads();

    {
        int jj = tid >> 2, part = tid & 3;
        int j  = j0 + jj;
        float s = 0.f;
        if (j < NN) {
            const float4* xp4 = (const float4*)(g_XL + (size_t)j * DD + h * CC + part * 32);
#pragma unroll
            for (int q = 0; q < 8; q++) {
                float4 xv = xp4[q];
                const float* ap = att_s + part * 32 + q * 4;
                s = fmaf(ap[0], xv.x, s);
                s = fmaf(ap[1], xv.y, s);
                s = fmaf(ap[2], xv.z, s);
                s = fmaf(ap[3], xv.w, s);
            }
        }
        alp[jj][part] = s;
    }
    __syncthreads();
    if (tid < 32) AL_s[tid] = alp[tid][0] + alp[tid][1] + alp[tid][2] + alp[tid][3];
    __syncthreads();

    const int  gi = i0 + lrow;
    const int  gj = j0 + lrow;
    const bool iv = (gi < NN);
    const bool jv = (gj < NN);
    const float* xrp = g_XR + (size_t)gi * DD + h * CC;
    const float* xlp = g_XL + (size_t)gj * DD + h * CC;

    float acc[2][4];
#pragma unroll
    for (int i = 0; i < 2; i++)
#pragma unroll
        for (int j = 0; j < 4; j++) acc[i][j] = 0.f;

    float4 ra = iv ? *(const float4*)(xrp + lq) : make_float4(0, 0, 0, 0);
    float4 rb = jv ? *(const float4*)(xlp + lq) : make_float4(0, 0, 0, 0);

    for (int k0 = 0; k0 < CC; k0 += 16) {
        As[lq + 0][lrow] = ra.x; As[lq + 1][lrow] = ra.y;
        As[lq + 2][lrow] = ra.z; As[lq + 3][lrow] = ra.w;
        Bs[lq + 0][lrow] = rb.x; Bs[lq + 1][lrow] = rb.y;
        Bs[lq + 2][lrow] = rb.z; Bs[lq + 3][lrow] = rb.w;
        __syncthreads();

        if (k0 + 16 < CC) {
            ra = iv ? *(const float4*)(xrp + k0 + 16 + lq) : make_float4(0, 0, 0, 0);
            rb = jv ? *(const float4*)(xlp + k0 + 16 + lq) : make_float4(0, 0, 0, 0);
        }

#pragma unroll
        for (int k = 0; k < 16; k++) {
            float a0 = As[k][ty * 2 + 0];
            float a1 = As[k][ty * 2 + 1];
            float4 b4 = *(const float4*)&Bs[k][tx << 2];
            float bv[4] = {b4.x, b4.y, b4.z, b4.w};
            float ac = att_s[k0 + k];
#pragma unroll
            for (int j = 0; j < 4; j++) {
                float t0 = a0 + bv[j];
                float t1 = a1 + bv[j];
                acc[0][j] = fmaf(ac, fabsf(t0), acc[0][j]);
                acc[1][j] = fmaf(ac, fabsf(t1), acc[1][j]);
            }
        }
        __syncthreads();
    }

#pragma unroll
    for (int ii = 0; ii < 2; ii++) {
        int i = i0 + ty * 2 + ii;
        if (i >= NN) continue;
        float* row = g_S + (size_t)(h * NN + i) * NPJ;
#pragma unroll
        for (int jj = 0; jj < 4; jj++) {
            int j = j0 + (tx << 2) + jj;
            if (j < NN)
                row[j] = fmaf(0.4f, acc[ii][jj], 0.6f * AL_s[(tx << 2) + jj]);
        }
    }
}

// ---------------------------------------------------------------------------
// Alpha normalization in place: g_S row -> count-weighted softmax alphas.
// grid (26, 8), 256 threads; warp per destination row.
// Rows j in [NN, NPJ) get alpha 0 (count 0).
// ---------------------------------------------------------------------------
__global__ void __launch_bounds__(256) k_norm() {
    const int h    = blockIdx.y;
    const int i    = blockIdx.x * 8 + (threadIdx.x >> 5);
    const int lane = threadIdx.x & 31;
    if (i >= NN) return;

    float*     srow = g_S + (size_t)(h * NN + i) * NPJ;
    const int* crow = g_cnt + i * NPJ;

    float sv[7], cv[7];
    float mx = -FLT_MAX;
#pragma unroll
    for (int t = 0; t < 7; t++) {
        int j = lane + t * 32;
        int c = crow[j];
        float s = (c > 0) ? srow[j] : -1e30f;
        sv[t] = s; cv[t] = (float)c;
        mx = fmaxf(mx, s);
    }
#pragma unroll
    for (int o = 16; o; o >>= 1) mx = fmaxf(mx, __shfl_xor_sync(0xffffffffu, mx, o));
    float ds = 0.f;
#pragma unroll
    for (int t = 0; t < 7; t++) ds += cv[t] * __expf(sv[t] - mx);
#pragma unroll
    for (int o = 16; o; o >>= 1) ds += __shfl_xor_sync(0xffffffffu, ds, o);
    float inv = 1.f / (ds + 1e-16f);
#pragma unroll
    for (int t = 0; t < 7; t++)
        srow[lane + t * 32] = cv[t] * __expf(sv[t] - mx) * inv;
}

// ---------------------------------------------------------------------------
// Aggregation GEMM: OUT[i][h*CC+n] = sum_j alpha[h,i,j] * XL[j][h*CC+n] + bias
// Tile 32i x 64n, K = NPJ = 224; 128 threads, microtile 2i x 8n.
// grid = (7 i-tiles, 2 n-tiles, 8 heads) = 112 blocks.
// ---------------------------------------------------------------------------
__global__ void __launch_bounds__(128) k_aggemm(const float* __restrict__ bias,
                                                int relu, int dst_sel) {
    float*    OUT = dst_sel ? g_H2 : g_H;
    const int h   = blockIdx.z;
    const int i0  = blockIdx.x * 32;
    const int n0  = blockIdx.y * 64;
    const int tid = threadIdx.x;
    const int tx  = tid & 7;          // 8  -> n octet (split 4+4)
    const int ty  = tid >> 3;         // 16 -> 2 i rows each

    __shared__ float As[16][32];      // alpha chunk [k][i]
    __shared__ float Bs[16][64];      // XL    chunk [k][n]

    // A staging: ar = i row, akq = k quad
    const int  ar  = tid & 31;
    const int  akq = (tid >> 5) << 2;
    const bool iv  = (i0 + ar) < NN;
    const float* arow = g_S + (size_t)(h * NN + i0 + ar) * NPJ;

    // B staging: bk = k row (0..7, +8), bn = n quad
    const int bk = tid >> 4;          // 0..7
    const int bn = (tid & 15) << 2;   // 0,4,...,60

    float acc[2][8];
#pragma unroll
    for (int i = 0; i < 2; i++)
#pragma unroll
        for (int j = 0; j < 8; j++) acc[i][j] = 0.f;

    // prefetch chunk 0
    float4 ra = iv ? *(const float4*)(arow + akq) : make_float4(0, 0, 0, 0);
    int jb0 = bk, jb1 = bk + 8;
    float4 rb0 = (jb0 < NN) ? *(const float4*)(g_XL + (size_t)jb0 * DD + h * CC + n0 + bn)
                            : make_float4(0, 0, 0, 0);
    float4 rb1 = (jb1 < NN) ? *(const float4*)(g_XL + (size_t)jb1 * DD + h * CC + n0 + bn)
                            : make_float4(0, 0, 0, 0);

    for (int k0 = 0; k0 < NPJ; k0 += 16) {
        As[akq + 0][ar] = ra.x; As[akq + 1][ar] = ra.y;
        As[akq + 2][ar] = ra.z; As[akq + 3][ar] = ra.w;
        *(float4*)&Bs[bk][bn]     = rb0;
        *(float4*)&Bs[bk + 8][bn] = rb1;
        __syncthreads();

        if (k0 + 16 < NPJ) {
            ra = iv ? *(const float4*)(arow + k0 + 16 + akq) : make_float4(0, 0, 0, 0);
            int j0n = k0 + 16 + bk, j1n = k0 + 24 + bk;
            rb0 = (j0n < NN) ? *(const float4*)(g_XL + (size_t)j0n * DD + h * CC + n0 + bn)
                             : make_float4(0, 0, 0, 0);
            rb1 = (j1n < NN) ? *(const float4*)(g_XL + (size_t)j1n * DD + h * CC + n0 + bn)
                             : make_float4(0, 0, 0, 0);
        }

#pragma unroll
        for (int k = 0; k < 16; k++) {
            float a0 = As[k][ty * 2 + 0];
            float a1 = As[k][ty * 2 + 1];
            float4 v0 = *(const float4*)&Bs[k][tx * 4];        // cols tx*4..+3
            float4 v1 = *(const float4*)&Bs[k][32 + tx * 4];   // cols 32+tx*4..+3
            acc[0][0] = fmaf(a0, v0.x, acc[0][0]);
            acc[0][1] = fmaf(a0, v0.y, acc[0][1]);
            acc[0][2] = fmaf(a0, v0.z, acc[0][2]);
            acc[0][3] = fmaf(a0, v0.w, acc[0][3]);
            acc[0][4] = fmaf(a0, v1.x, acc[0][4]);
            acc[0][5] = fmaf(a0, v1.y, acc[0][5]);
            acc[0][6] = fmaf(a0, v1.z, acc[0][6]);
            acc[0][7] = fmaf(a0, v1.w, acc[0][7]);
            acc[1][0] = fmaf(a1, v0.x, acc[1][0]);
            acc[1][1] = fmaf(a1, v0.y, acc[1][1]);
            acc[1][2] = fmaf(a1, v0.z, acc[1][2]);
            acc[1][3] = fmaf(a1, v0.w, acc[1][3]);
            acc[1][4] = fmaf(a1, v1.x, acc[1][4]);
            acc[1][5] = fmaf(a1, v1.y, acc[1][5]);
            acc[1][6] = fmaf(a1, v1.z, acc[1][6]);
            acc[1][7] = fmaf(a1, v1.w, acc[1][7]);
        }
        __syncthreads();
    }

#pragma unroll
    for (int ii = 0; ii < 2; ii++) {
        int i = i0 + ty * 2 + ii;
        if (i >= NN) continue;
        float* orow = OUT + (size_t)i * DD + h * CC + n0;
        const float* bp = bias + h * CC + n0;
        float4 o0 = {acc[ii][0], acc[ii][1], acc[ii][2], acc[ii][3]};
        float4 o1 = {acc[ii][4], acc[ii][5], acc[ii][6], acc[ii][7]};
        float4 b0 = *(const float4*)(bp + tx * 4);
        float4 b1 = *(const float4*)(bp + 32 + tx * 4);
        o0.x += b0.x; o0.y += b0.y; o0.z += b0.z; o0.w += b0.w;
        o1.x += b1.x; o1.y += b1.y; o1.z += b1.z; o1.w += b1.w;
        if (relu) {
            o0.x = fmaxf(o0.x, 0.f); o0.y = fmaxf(o0.y, 0.f);
            o0.z = fmaxf(o0.z, 0.f); o0.w = fmaxf(o0.w, 0.f);
            o1.x = fmaxf(o1.x, 0.f); o1.y = fmaxf(o1.y, 0.f);
            o1.z = fmaxf(o1.z, 0.f); o1.w = fmaxf(o1.w, 0.f);
        }
        *(float4*)(orow + tx * 4)      = o0;
        *(float4*)(orow + 32 + tx * 4) = o1;
    }
}

// ---------------------------------------------------------------------------
// Pooling (8 blocks x 128): avg[d] = sum_i w_i * H2[i][d]; re-zeroes g_cnt.
// ---------------------------------------------------------------------------
__global__ void k_pool() {
    int d = blockIdx.x * blockDim.x + threadIdx.x;
    float s = 0.f;
#pragma unroll 8
    for (int i = 0; i < NN - 1; i++) s += g_H2[i * DD + d];
    s = s * (1.f / 300.f) + g_H2[(NN - 1) * DD + d] * (1.f / 3.f);
    g_avg[d] = s;
    for (int idx = d; idx < NN * NPJ; idx += 1024) g_cnt[idx] = 0;
}

// ---------------------------------------------------------------------------
// Classifier: out[c] = avg . clfW[c] + clfb[c]
// ---------------------------------------------------------------------------
__global__ void k_clf(const float* __restrict__ W, const float* __restrict__ b,
                      float* __restrict__ out) {
    __shared__ float red0[8], red1[8];
    int tid = threadIdx.x;
    float p0 = 0.f, p1 = 0.f;
    for (int d = tid; d < DD; d += 256) {
        float a = g_avg[d];
        p0 = fmaf(a, W[d], p0);
        p1 = fmaf(a, W[DD + d], p1);
    }
    for (int o = 16; o; o >>= 1) {
        p0 += __shfl_xor_sync(0xffffffffu, p0, o);
        p1 += __shfl_xor_sync(0xffffffffu, p1, o);
    }
    if ((tid & 31) == 0) { red0[tid >> 5] = p0; red1[tid >> 5] = p1; }
    __syncthreads();
    if (tid == 0) {
        float s0 = 0.f, s1 = 0.f;
        for (int w = 0; w < 8; w++) { s0 += red0[w]; s1 += red1[w]; }
        out[0] = s0 + b[0];
        out[1] = s1 + b[1];
    }
}

// ---------------------------------------------------------------------------
extern "C" void kernel_launch(void* const* d_in, const int* in_sizes, int n_in,
                              void* d_out, int out_size) {
    const float* x     = (const float*)d_in[0];
    const int*   ebuf  = (const int*)  d_in[1];
    const float* W1l   = (const float*)d_in[2];
    const float* b1l   = (const float*)d_in[3];
    const float* W1r   = (const float*)d_in[4];
    const float* b1r   = (const float*)d_in[5];
    const float* att1  = (const float*)d_in[6];
    const float* bias1 = (const float*)d_in[7];
    const float* W2l   = (const float*)d_in[8];
    const float* b2l   = (const float*)d_in[9];
    const float* W2r   = (const float*)d_in[10];
    const float* b2r   = (const float*)d_in[11];
    const float* att2  = (const float*)d_in[12];
    const float* bias2 = (const float*)d_in[13];
    const float* clfW  = (const float*)d_in[14];
    const float* clfb  = (const float*)d_in[15];
    float* out = (float*)d_out;

    k_count<<<(EE + NN + 255) / 256, 256>>>(ebuf);

    dim3 gg(4, 16, 2);          // GEMM: m-tiles x n-tiles x {l,r}
    dim3 gs(7, 7, HH);          // score: i-tiles x j-tiles x heads
    dim3 gn(26, HH);            // norm:  i-tiles x heads
    dim3 ga(7, 2, HH);          // agg:   i-tiles x n-tiles x heads

    // layer 1
    k_gemm_mma<<<gg, 256>>>(x, W1l, b1l, W1r, b1r);
    k_score   <<<gs, 128>>>(att1);
    k_norm    <<<gn, 256>>>();
    k_aggemm  <<<ga, 128>>>(bias1, /*relu=*/1, /*dst=*/0);

    // layer 2
    k_gemm_mma<<<gg, 256>>>(nullptr, W2l, b2l, W2r, b2r);
    k_score   <<<gs, 128>>>(att2);
    k_norm    <<<gn, 256>>>();
    k_aggemm  <<<ga, 128>>>(bias2, /*relu=*/0, /*dst=*/1);

    // pooling (+ g_cnt reset) and classifier
    k_pool<<<8, 128>>>();
    k_clf <<<1, 256>>>(clfW, clfb, out);
}